// round 16
// baseline (speedup 1.0000x reference)
#include <cuda_runtime.h>
#include <math_constants.h>

#define HFEAT 200
#define WFEAT 320
#define HWFEAT (HFEAT * WFEAT)      // 64000 pixels
#define HW4 (HWFEAT / 4)            // 16000 pixel-quads
#define CFEAT 256
#define NROI 128
#define MSZ 14
#define NBIN (MSZ * MSZ)            // 196
#define NCB 16                      // channel blocks (16 channels each)
#define CPB 16
#define NCAND (NROI * 4)            // 512 candidate points per bin
#define NSEED 8                     // rois used for seeding

// Scratch (static device arrays — no allocation)
__device__ __align__(16) float g_Mb[HWFEAT * NCB];   // [pix][cb] per-pixel 16-ch maxes (4 MB)
__device__ __align__(16) float g_best[NBIN];         // per-bin running exact max

// ---------------------------------------------------------------------------
__device__ __forceinline__ void atomicMaxFloat(float* addr, float val) {
    if (val >= 0.0f) {
        atomicMax((int*)addr, __float_as_int(val));
    } else {
        atomicMin((unsigned int*)addr, __float_as_uint(val));
    }
}

// ---------------------------------------------------------------------------
// Geometry: replicate the reference bilinear setup exactly
// (corner indices clamped FIRST, weights computed from clamped corners).
// rois row loaded as a single float4 (16B-aligned [128,4] tensor).
// ---------------------------------------------------------------------------
struct Geom {
    int o11, o12, o21, o22;
    float wy_lo, wy_hi, wx_lo, wx_hi;
    bool wok;   // weights form a convex combination (clamp did not trigger)
};

__device__ __forceinline__ Geom make_geom(const float* __restrict__ rois,
                                          int r, int s, int m, int n) {
    float4 rr = __ldg(reinterpret_cast<const float4*>(rois) + r);
    float sh = (rr.z - rr.x) / 14.0f;
    float sw = (rr.w - rr.y) / 14.0f;
    float fy = (s >> 1) ? (2.0f / 3.0f) : (1.0f / 3.0f);
    float fx = (s & 1)  ? (2.0f / 3.0f) : (1.0f / 3.0f);
    float y = (rr.x + sh * (float)m) + sh * fy;
    float x = (rr.y + sw * (float)n) + sw * fx;

    int yf = (int)floorf(y);
    int xf = (int)floorf(x);
    int y1c = min(max(yf, 0), HFEAT - 1);
    int y2c = min(max(yf + 1, 0), HFEAT - 1);
    int x1c = min(max(xf, 0), WFEAT - 1);
    int x2c = min(max(xf + 1, 0), WFEAT - 1);

    Geom g;
    g.wy_lo = y - (float)y1c;
    g.wy_hi = (float)y2c - y;
    g.wx_lo = x - (float)x1c;
    g.wx_hi = (float)x2c - x;
    g.wok = (g.wy_lo >= 0.0f) && (g.wy_lo <= 1.0f) && (g.wy_hi >= 0.0f) && (g.wy_hi <= 1.0f) &&
            (g.wx_lo >= 0.0f) && (g.wx_lo <= 1.0f) && (g.wx_hi >= 0.0f) && (g.wx_hi <= 1.0f);
    g.o11 = y1c * WFEAT + x1c;
    g.o12 = y1c * WFEAT + x2c;
    g.o21 = y2c * WFEAT + x1c;
    g.o22 = y2c * WFEAT + x2c;
    return g;
}

__device__ __forceinline__ float bilin(const float* __restrict__ base, const Geom& g) {
    float a = __ldg(base + g.o11);
    float b = __ldg(base + g.o12);
    float c = __ldg(base + g.o21);
    float d = __ldg(base + g.o22);
    return g.wy_hi * (g.wx_hi * a + g.wx_lo * b) +
           g.wy_lo * (g.wx_hi * c + g.wx_lo * d);
}

// ---------------------------------------------------------------------------
// Pass 1: per-pixel 16-channel-block maxes. (unchanged — measured good)
// grid = 1000 blocks; block = 256 threads = 16 cb x 16 pixel-quads.
// ---------------------------------------------------------------------------
__global__ void __launch_bounds__(256) k_colmax(const float4* __restrict__ f4) {
    __shared__ float s[64][NCB + 1];    // +1 pad: kill store bank conflicts

    if (blockIdx.x == 0 && threadIdx.x < NBIN)
        g_best[threadIdx.x] = -CUDART_INF_F;

    int qi = threadIdx.x & 15;          // quad within block (0..15)
    int cb = threadIdx.x >> 4;          // channel block (0..15)
    int pg = blockIdx.x * 16 + qi;      // global pixel quad (0..15999)

    const float4* p = f4 + (size_t)(cb * CPB) * HW4 + pg;
    float4 m = make_float4(-CUDART_INF_F, -CUDART_INF_F, -CUDART_INF_F, -CUDART_INF_F);
#pragma unroll
    for (int j = 0; j < CPB; j++) {
        float4 v = __ldg(p + (size_t)j * HW4);
        m.x = fmaxf(m.x, v.x); m.y = fmaxf(m.y, v.y);
        m.z = fmaxf(m.z, v.z); m.w = fmaxf(m.w, v.w);
    }
    int lpx = qi * 4;                   // local pixel 0..63
    s[lpx + 0][cb] = m.x;
    s[lpx + 1][cb] = m.y;
    s[lpx + 2][cb] = m.z;
    s[lpx + 3][cb] = m.w;
    __syncthreads();

    // write 64 px * 16 cb = 256 float4, one per thread, coalesced
    int px  = threadIdx.x >> 2;         // 0..63
    int cb0 = (threadIdx.x & 3) * 4;    // 0,4,8,12
    float4 o = make_float4(s[px][cb0], s[px][cb0 + 1], s[px][cb0 + 2], s[px][cb0 + 3]);
    float4* dst = reinterpret_cast<float4*>(g_Mb + ((size_t)blockIdx.x * 64) * NCB);
    dst[threadIdx.x] = o;
}

// ---------------------------------------------------------------------------
// Seed pass (unchanged — measured good): exact evaluation of NSEED candidate
// points per bin -> tight exact lower bounds in g_best.
// ---------------------------------------------------------------------------
__global__ void __launch_bounds__(NSEED * 32) k_seed(const float* __restrict__ f,
                                                     const float* __restrict__ rois) {
    int bin  = blockIdx.x;
    int w    = threadIdx.x >> 5;        // roi 0..NSEED-1
    int lane = threadIdx.x & 31;
    int m = bin / MSZ;
    int n = bin - m * MSZ;

    Geom g = make_geom(rois, w, 0, m, n);

    float vmax = -CUDART_INF_F;
#pragma unroll
    for (int ci = 0; ci < CFEAT / 32; ci++) {
        const float* fc = f + (size_t)(ci * 32 + lane) * HWFEAT;
        vmax = fmaxf(vmax, bilin(fc, g));
    }
#pragma unroll
    for (int o = 16; o; o >>= 1)
        vmax = fmaxf(vmax, __shfl_xor_sync(0xffffffffu, vmax, o));
    if (lane == 0) atomicMaxFloat(&g_best[bin], vmax);
}

// ---------------------------------------------------------------------------
// Screened point pass — THE CHANGE THIS ROUND: one warp screens TWO
// candidates (lanes 0-15 = cand A's 16 block bounds, lanes 16-31 = cand B's),
// halving the block count (grid (196,32), ~6 waves instead of ~12) at the
// same per-warp latency chain. Survivors (rare) get the measured-good
// per-block eval, geometry broadcast by shuffle from the owning half.
// g_best holds only exact values => pruning exact & deterministic.
// ---------------------------------------------------------------------------
__global__ void __launch_bounds__(256) k_points(const float* __restrict__ f,
                                                const float* __restrict__ rois) {
    int bin  = blockIdx.x;                          // 0..195
    int pair = blockIdx.y * 8 + (threadIdx.x >> 5); // 0..255 (2 candidates each)
    int lane = threadIdx.x & 31;
    int half = lane >> 4;                           // 0 = cand A, 1 = cand B
    int cb   = lane & 15;                           // channel block for screen

    int cand = pair * 2 + half;                     // 0..511
    int m = bin / MSZ;
    int n = bin - m * MSZ;

    Geom g = make_geom(rois, cand >> 2, cand & 3, m, n);

    float best = __ldg(&g_best[bin]);   // seeded exact lower bound

    // fine screen: every lane bounds one (candidate, channel-block)
    float m11 = __ldg(&g_Mb[(size_t)g.o11 * NCB + cb]);
    float m12 = __ldg(&g_Mb[(size_t)g.o12 * NCB + cb]);
    float m21 = __ldg(&g_Mb[(size_t)g.o21 * NCB + cb]);
    float m22 = __ldg(&g_Mb[(size_t)g.o22 * NCB + cb]);
    float ub = g.wy_hi * (g.wx_hi * m11 + g.wx_lo * m12) +
               g.wy_lo * (g.wx_hi * m21 + g.wx_lo * m22);
    bool need = (!g.wok) || (ub > best);    // !wok marks all 16 lanes of the half

    unsigned bal = __ballot_sync(0xffffffffu, need);
    if (!bal) return;

    float vmax = -CUDART_INF_F;
    bool  wrote = false;

#pragma unroll
    for (int h = 0; h < 2; h++) {
        unsigned mask = (h ? (bal >> 16) : bal) & 0xFFFFu;
        if (!mask) continue;

        // broadcast candidate h's geometry from its owning half
        int src = h * 16;
        Geom g2;
        g2.o11   = __shfl_sync(0xffffffffu, g.o11, src);
        g2.o12   = __shfl_sync(0xffffffffu, g.o12, src);
        g2.o21   = __shfl_sync(0xffffffffu, g.o21, src);
        g2.o22   = __shfl_sync(0xffffffffu, g.o22, src);
        g2.wy_lo = __shfl_sync(0xffffffffu, g.wy_lo, src);
        g2.wy_hi = __shfl_sync(0xffffffffu, g.wy_hi, src);
        g2.wx_lo = __shfl_sync(0xffffffffu, g.wx_lo, src);
        g2.wx_hi = __shfl_sync(0xffffffffu, g.wx_hi, src);

        // evaluate surviving blocks, two at a time across the warp
        float v = -CUDART_INF_F;
        while (mask) {
            int cb0 = __ffs(mask) - 1;
            mask &= mask - 1;
            int cb1 = cb0;
            if (mask) { cb1 = __ffs(mask) - 1; mask &= mask - 1; }
            int cbe = (lane < 16) ? cb0 : cb1;
            const float* fc = f + (size_t)(cbe * CPB + cb) * HWFEAT;
            v = fmaxf(v, bilin(fc, g2));
        }
#pragma unroll
        for (int o = 16; o; o >>= 1)
            v = fmaxf(v, __shfl_xor_sync(0xffffffffu, v, o));
        vmax = fmaxf(vmax, v);
        wrote = true;
    }
    if (wrote && lane == 0) atomicMaxFloat(&g_best[bin], vmax);
}

// ---------------------------------------------------------------------------
// Broadcast g_best[196] to out[R, C, 14, 14]. Exact R13 version (best
// measured total; bcast is at a ~3.3TB/s write floor — two different
// front-ends measured identically, so leave it alone).
// ---------------------------------------------------------------------------
__global__ void __launch_bounds__(256) k_bcast(float4* __restrict__ out) {
    __shared__ float4 sb[NBIN / 4];     // 49 float4
    if (threadIdx.x < NBIN / 4)
        sb[threadIdx.x] = reinterpret_cast<const float4*>(g_best)[threadIdx.x];
    __syncthreads();
    int base = blockIdx.x * 2048 + threadIdx.x;
    int idx  = base % (NBIN / 4);       // one division per thread
#pragma unroll
    for (int k = 0; k < 8; k++) {
        out[base + k * 256] = sb[idx];
        idx += 256 % (NBIN / 4);        // 256 % 49 = 11 (compile-time)
        if (idx >= NBIN / 4) idx -= NBIN / 4;
    }
}

// ---------------------------------------------------------------------------
extern "C" void kernel_launch(void* const* d_in, const int* in_sizes, int n_in,
                              void* d_out, int out_size) {
    const float* feature = (const float*)d_in[0];   // [1,256,200,320] f32
    const float* rois    = (const float*)d_in[1];   // [128,4] f32
    float* out           = (float*)d_out;           // [128,256,14,14] f32

    // Pass 1: per-pixel 16-channel block maxes (+ g_best init)
    k_colmax<<<HW4 / 16, 256>>>((const float4*)feature);

    // Seed: exact per-bin lower bounds from 8 candidates
    k_seed<<<NBIN, NSEED * 32>>>(feature, rois);

    // Screened pass: 2 candidates per warp -> half the blocks/waves
    dim3 g2(NBIN, NCAND / 16);
    k_points<<<g2, 256>>>(feature, rois);

    // Broadcast result
    k_bcast<<<784, 256>>>((float4*)out);
}